// round 12
// baseline (speedup 1.0000x reference)
#include <cuda_runtime.h>
#include <cstdint>

#define NN 20000
#define EE 100000
#define CC 256
#define ED_ 16
#define RC 4
#define MROWS 80000

// Scratch (device globals: no allocation allowed)
__device__ float g_xl[(size_t)MROWS * CC];
__device__ float g_sums[(size_t)MROWS * CC];   // per-node MEAN after sage_agg
__device__ float g_inv[NN];
__device__ int   g_cnt[NN];
__device__ int   g_cur[NN];
__device__ int   g_off[NN];
__device__ int   g_eord[EE];

// ---------------------------------------------------------------------------
// packed fp32x2 helpers (SASS FFMA2) — proven in R10
__device__ __forceinline__ unsigned long long pk2(float lo, float hi) {
    unsigned long long r;
    asm("mov.b64 %0, {%1, %2};" : "=l"(r) : "f"(lo), "f"(hi));
    return r;
}
__device__ __forceinline__ void upk2(unsigned long long v, float& lo, float& hi) {
    asm("mov.b64 {%0, %1}, %2;" : "=f"(lo), "=f"(hi) : "l"(v));
}
__device__ __forceinline__ void ffma2(unsigned long long& d, unsigned long long a,
                                      unsigned long long b) {
    asm("fma.rn.f32x2 %0, %1, %2, %0;" : "+l"(d) : "l"(a), "l"(b));
}

// ---------------------------------------------------------------------------
// CSR build: reset, count, scan(+inv), place
__global__ void sage_rst() {
    int n = blockIdx.x * blockDim.x + threadIdx.x;
    if (n < NN) { g_cnt[n] = 0; g_cur[n] = 0; }
}

__global__ void sage_cnt(const int* __restrict__ ei) {
    int e = blockIdx.x * blockDim.x + threadIdx.x;
    if (e < EE) {
        int d = ei[EE + e];
        d = (d >= 0 && d < NN) ? d : 0;
        atomicAdd(&g_cnt[d], 1);
    }
}

#define SCAN_T 1024
__global__ __launch_bounds__(SCAN_T) void sage_scan() {
    __shared__ int ps[SCAN_T];
    const int t = threadIdx.x;
    const int CHN = (NN + SCAN_T - 1) / SCAN_T;   // 20
    const int base = t * CHN;
    int sum = 0;
    for (int i = 0; i < CHN; i++) {
        int n = base + i;
        if (n < NN) sum += g_cnt[n];
    }
    ps[t] = sum;
    __syncthreads();
    for (int d = 1; d < SCAN_T; d <<= 1) {
        int v = (t >= d) ? ps[t - d] : 0;
        __syncthreads();
        ps[t] += v;
        __syncthreads();
    }
    int run = (t == 0) ? 0 : ps[t - 1];           // exclusive prefix of chunk
    for (int i = 0; i < CHN; i++) {
        int n = base + i;
        if (n < NN) {
            int c = g_cnt[n];
            g_off[n] = run;
            run += c;
            g_inv[n] = 1.0f / fmaxf((float)c, 1.0f);
        }
    }
}

__global__ void sage_place(const int* __restrict__ ei) {
    int e = blockIdx.x * blockDim.x + threadIdx.x;
    if (e < EE) {
        int d = ei[EE + e];
        d = (d >= 0 && d < NN) ? d : 0;
        int p = g_off[d] + atomicAdd(&g_cur[d], 1);
        g_eord[p] = e;
    }
}

// ---------------------------------------------------------------------------
// SGEMM 1 (R10 exact): g_xl = x @ lin_W + lin_b  (M=80000,N=256,K=256)
#define BM 128
#define BN 64
#define BK 16

__global__ __launch_bounds__(256) void sage_g1(
    const float* __restrict__ A, const float* __restrict__ B,
    const float* __restrict__ bias) {
    __shared__ float As[BK][BM];
    __shared__ float Bs[BK][BN];
    const int bx = blockIdx.x, by = blockIdx.y;
    const int tid = threadIdx.x;
    const int tx = tid & 15, ty = tid >> 4;
    const int row0 = by * BM, col0 = bx * BN;

    unsigned long long acc[8][2];
#pragma unroll
    for (int i = 0; i < 8; i++) { acc[i][0] = 0ull; acc[i][1] = 0ull; }

    for (int kt = 0; kt < 256; kt += BK) {
#pragma unroll
        for (int i = 0; i < 2; i++) {
            int l = tid + i * 256;
            int ar = l >> 2, ac = (l & 3) * 4;
            float4 v = *(const float4*)&A[(size_t)(row0 + ar) * CC + kt + ac];
            As[ac + 0][ar] = v.x; As[ac + 1][ar] = v.y;
            As[ac + 2][ar] = v.z; As[ac + 3][ar] = v.w;
        }
        {
            int br = tid >> 4, bc = (tid & 15) * 4;
            *(float4*)&Bs[br][bc] =
                *(const float4*)&B[(size_t)(kt + br) * CC + col0 + bc];
        }
        __syncthreads();
#pragma unroll
        for (int k = 0; k < BK; k++) {
            float4 a0 = *(float4*)&As[k][ty * 8];
            float4 a1 = *(float4*)&As[k][ty * 8 + 4];
            unsigned long long b01 = *(unsigned long long*)&Bs[k][tx * 4];
            unsigned long long b23 = *(unsigned long long*)&Bs[k][tx * 4 + 2];
            float a[8] = {a0.x, a0.y, a0.z, a0.w, a1.x, a1.y, a1.z, a1.w};
#pragma unroll
            for (int i = 0; i < 8; i++) {
                unsigned long long ad = pk2(a[i], a[i]);
                ffma2(acc[i][0], ad, b01);
                ffma2(acc[i][1], ad, b23);
            }
        }
        __syncthreads();
    }
#pragma unroll
    for (int i = 0; i < 8; i++) {
        int m = row0 + ty * 8 + i;
        int n = col0 + tx * 4;
        float v0, v1, v2, v3;
        upk2(acc[i][0], v0, v1);
        upk2(acc[i][1], v2, v3);
        float4 o = make_float4(v0 + bias[n], v1 + bias[n + 1],
                               v2 + bias[n + 2], v3 + bias[n + 3]);
        *(float4*)&g_xl[(size_t)m * CC + n] = o;
    }
}

// ---------------------------------------------------------------------------
// SGEMM 2 (R10 exact, minus inv — g_sums already holds means):
// out = [mean | x] @ [[linl_W],[linr_W]] + linl_b, K=512
__global__ __launch_bounds__(256) void sage_g2(
    const float* __restrict__ X, const float* __restrict__ Wl,
    const float* __restrict__ Wr, const float* __restrict__ bl,
    float* __restrict__ Cout) {
    __shared__ float As[BK][BM];
    __shared__ float Bs[BK][BN];
    const int bx = blockIdx.x, by = blockIdx.y;
    const int tid = threadIdx.x;
    const int tx = tid & 15, ty = tid >> 4;
    const int row0 = by * BM, col0 = bx * BN;

    unsigned long long acc[8][2];
#pragma unroll
    for (int i = 0; i < 8; i++) { acc[i][0] = 0ull; acc[i][1] = 0ull; }

    for (int kt = 0; kt < 512; kt += BK) {
        const bool first = (kt < 256);
#pragma unroll
        for (int i = 0; i < 2; i++) {
            int l = tid + i * 256;
            int ar = l >> 2, ac = (l & 3) * 4;
            int m = row0 + ar;
            float4 v;
            if (first) {
                v = *(const float4*)&g_sums[(size_t)m * CC + kt + ac];
            } else {
                v = *(const float4*)&X[(size_t)m * CC + (kt - 256) + ac];
            }
            As[ac + 0][ar] = v.x; As[ac + 1][ar] = v.y;
            As[ac + 2][ar] = v.z; As[ac + 3][ar] = v.w;
        }
        {
            int br = tid >> 4, bc = (tid & 15) * 4;
            const float* Bsrc = first ? Wl : Wr;
            int kk = first ? (kt + br) : (kt - 256 + br);
            *(float4*)&Bs[br][bc] =
                *(const float4*)&Bsrc[(size_t)kk * CC + col0 + bc];
        }
        __syncthreads();
#pragma unroll
        for (int k = 0; k < BK; k++) {
            float4 a0 = *(float4*)&As[k][ty * 8];
            float4 a1 = *(float4*)&As[k][ty * 8 + 4];
            unsigned long long b01 = *(unsigned long long*)&Bs[k][tx * 4];
            unsigned long long b23 = *(unsigned long long*)&Bs[k][tx * 4 + 2];
            float a[8] = {a0.x, a0.y, a0.z, a0.w, a1.x, a1.y, a1.z, a1.w};
#pragma unroll
            for (int i = 0; i < 8; i++) {
                unsigned long long ad = pk2(a[i], a[i]);
                ffma2(acc[i][0], ad, b01);
                ffma2(acc[i][1], ad, b23);
            }
        }
        __syncthreads();
    }
#pragma unroll
    for (int i = 0; i < 8; i++) {
        int m = row0 + ty * 8 + i;
        int n = col0 + tx * 4;
        float v0, v1, v2, v3;
        upk2(acc[i][0], v0, v1);
        upk2(acc[i][1], v2, v3);
        float4 o = make_float4(v0 + bl[n], v1 + bl[n + 1],
                               v2 + bl[n + 2], v3 + bl[n + 3]);
        *(float4*)&Cout[(size_t)m * CC + n] = o;
    }
}

// ---------------------------------------------------------------------------
// CSR aggregation: one block per dst node; registers accumulate all 4 (r,ch)
// replicas; writes each g_sums row exactly once (already divided by count).
// Replaces zero_sums + 410M global fp32 atomics.
__global__ __launch_bounds__(256) void sage_agg(
    const float* __restrict__ edge_attr, const float* __restrict__ ew,
    const int* __restrict__ ei, const float* __restrict__ bond_W,
    const float* __restrict__ bond_b) {
    const int d = blockIdx.x;
    const int c = threadIdx.x;
    const int beg = g_off[d];
    const int end = (d == NN - 1) ? EE : g_off[d + 1];

    float bw[ED_];
#pragma unroll
    for (int k = 0; k < ED_; k++) bw[k] = bond_W[k * CC + c];
    const float bb = bond_b[c];

    float acc0 = 0.f, acc1 = 0.f, acc2 = 0.f, acc3 = 0.f;
    for (int p = beg; p < end; p++) {
        int e = g_eord[p];
        int s = ei[e];
        s = (s >= 0 && s < NN) ? s : 0;
        float emb = bb;
#pragma unroll
        for (int k = 0; k < ED_; k++)
            emb += edge_attr[(size_t)e * ED_ + k] * bw[k];
        float w0 = ew[e], w1 = ew[EE + e], w2 = ew[2 * EE + e],
              w3 = ew[3 * EE + e];
        const size_t sb = (size_t)s * CC + c;
        float t0 = g_xl[sb] + emb;
        float t1 = g_xl[sb + (size_t)NN * CC] + emb;
        float t2 = g_xl[sb + (size_t)2 * NN * CC] + emb;
        float t3 = g_xl[sb + (size_t)3 * NN * CC] + emb;
        const float iv = 0.70710678118654752f;
        acc0 += 0.5f * t0 * (1.0f + erff(t0 * iv)) * w0;
        acc1 += 0.5f * t1 * (1.0f + erff(t1 * iv)) * w1;
        acc2 += 0.5f * t2 * (1.0f + erff(t2 * iv)) * w2;
        acc3 += 0.5f * t3 * (1.0f + erff(t3 * iv)) * w3;
    }
    const float inv = g_inv[d];
    const size_t db = (size_t)d * CC + c;
    g_sums[db] = acc0 * inv;
    g_sums[db + (size_t)NN * CC] = acc1 * inv;
    g_sums[db + (size_t)2 * NN * CC] = acc2 * inv;
    g_sums[db + (size_t)3 * NN * CC] = acc3 * inv;
}

// ---------------------------------------------------------------------------
extern "C" void kernel_launch(void* const* d_in, const int* in_sizes, int n_in,
                              void* d_out, int out_size) {
    const float* x         = (const float*)d_in[0];
    const float* edge_attr = (const float*)d_in[1];
    const float* edge_w    = (const float*)d_in[2];
    const float* lin_W     = (const float*)d_in[3];
    const float* lin_b     = (const float*)d_in[4];
    const float* linl_W    = (const float*)d_in[5];
    const float* linl_b    = (const float*)d_in[6];
    const float* linr_W    = (const float*)d_in[7];
    const float* bond_W    = (const float*)d_in[8];
    const float* bond_b    = (const float*)d_in[9];
    const int*   eidx      = (const int*)d_in[10];
    float* out = (float*)d_out;

    sage_rst<<<(NN + 255) / 256, 256>>>();
    sage_cnt<<<(EE + 255) / 256, 256>>>(eidx);
    sage_scan<<<1, SCAN_T>>>();
    sage_place<<<(EE + 255) / 256, 256>>>(eidx);
    sage_g1<<<dim3(CC / BN, MROWS / BM), 256>>>(x, lin_W, lin_b);
    sage_agg<<<NN, 256>>>(edge_attr, edge_w, eidx, bond_W, bond_b);
    sage_g2<<<dim3(CC / BN, MROWS / BM), 256>>>(x, linl_W, linr_W, linl_b, out);
}

// round 13
// speedup vs baseline: 1.0081x; 1.0081x over previous
#include <cuda_runtime.h>
#include <cstdint>

#define NN 20000
#define EE 100000
#define CC 256
#define ED_ 16
#define RC 4
#define MROWS 80000

// Scratch (device globals: no allocation allowed)
__device__ float g_xl[(size_t)MROWS * CC];
__device__ float g_sums[(size_t)MROWS * CC];   // per-node MEAN after sage_agg
__device__ float g_emb[(size_t)EE * CC];       // bond encoder output
__device__ float g_inv[NN];
__device__ int   g_cnt[NN];
__device__ int   g_cur[NN];
__device__ int   g_off[NN];
__device__ int   g_eord[EE];

// ---------------------------------------------------------------------------
// packed fp32x2 helpers (SASS FFMA2) — proven in R10
__device__ __forceinline__ unsigned long long pk2(float lo, float hi) {
    unsigned long long r;
    asm("mov.b64 %0, {%1, %2};" : "=l"(r) : "f"(lo), "f"(hi));
    return r;
}
__device__ __forceinline__ void upk2(unsigned long long v, float& lo, float& hi) {
    asm("mov.b64 {%0, %1}, %2;" : "=f"(lo), "=f"(hi) : "l"(v));
}
__device__ __forceinline__ void ffma2(unsigned long long& d, unsigned long long a,
                                      unsigned long long b) {
    asm("fma.rn.f32x2 %0, %1, %2, %0;" : "+l"(d) : "l"(a), "l"(b));
}

__device__ __forceinline__ float gelu(float t) {
    return 0.5f * t * (1.0f + erff(t * 0.70710678118654752f));
}

// ---------------------------------------------------------------------------
// CSR build: reset, count, scan(+inv), place  (proven in R12)
__global__ void sage_rst() {
    int n = blockIdx.x * blockDim.x + threadIdx.x;
    if (n < NN) { g_cnt[n] = 0; g_cur[n] = 0; }
}

__global__ void sage_cnt(const int* __restrict__ ei) {
    int e = blockIdx.x * blockDim.x + threadIdx.x;
    if (e < EE) {
        int d = ei[EE + e];
        d = (d >= 0 && d < NN) ? d : 0;
        atomicAdd(&g_cnt[d], 1);
    }
}

#define SCAN_T 1024
__global__ __launch_bounds__(SCAN_T) void sage_scan() {
    __shared__ int ps[SCAN_T];
    const int t = threadIdx.x;
    const int CHN = (NN + SCAN_T - 1) / SCAN_T;
    const int base = t * CHN;
    int sum = 0;
    for (int i = 0; i < CHN; i++) {
        int n = base + i;
        if (n < NN) sum += g_cnt[n];
    }
    ps[t] = sum;
    __syncthreads();
    for (int d = 1; d < SCAN_T; d <<= 1) {
        int v = (t >= d) ? ps[t - d] : 0;
        __syncthreads();
        ps[t] += v;
        __syncthreads();
    }
    int run = (t == 0) ? 0 : ps[t - 1];
    for (int i = 0; i < CHN; i++) {
        int n = base + i;
        if (n < NN) {
            int c = g_cnt[n];
            g_off[n] = run;
            run += c;
            g_inv[n] = 1.0f / fmaxf((float)c, 1.0f);
        }
    }
}

__global__ void sage_place(const int* __restrict__ ei) {
    int e = blockIdx.x * blockDim.x + threadIdx.x;
    if (e < EE) {
        int d = ei[EE + e];
        d = (d >= 0 && d < NN) ? d : 0;
        int p = g_off[d] + atomicAdd(&g_cur[d], 1);
        g_eord[p] = e;
    }
}

// ---------------------------------------------------------------------------
// Bond encoder precompute: g_emb[e][c] = bond_b[c] + sum_k ea[e][k]*bond_W[k][c]
__global__ __launch_bounds__(256) void sage_emb(
    const float* __restrict__ ea, const float* __restrict__ bw,
    const float* __restrict__ bb) {
    int idx = blockIdx.x * 256 + threadIdx.x;   // EE*64 total
    int e = idx >> 6, cq = (idx & 63) * 4;
    if (e < EE) {
        float4 acc = *(const float4*)&bb[cq];
#pragma unroll
        for (int k = 0; k < ED_; k++) {
            float a = ea[(size_t)e * ED_ + k];
            float4 w = *(const float4*)&bw[k * CC + cq];
            acc.x += a * w.x; acc.y += a * w.y;
            acc.z += a * w.z; acc.w += a * w.w;
        }
        *(float4*)&g_emb[(size_t)e * CC + cq] = acc;
    }
}

// ---------------------------------------------------------------------------
// Double-buffered f32x2 SGEMM 1: g_xl = x @ lin_W + lin_b (M=80000,N=256,K=256)
#define BM 128
#define BN 64
#define BK 16

__global__ __launch_bounds__(256) void sage_g1(
    const float* __restrict__ A, const float* __restrict__ B,
    const float* __restrict__ bias) {
    __shared__ float As[2][BK][BM];
    __shared__ float Bs[2][BK][BN];
    const int bx = blockIdx.x, by = blockIdx.y;
    const int tid = threadIdx.x;
    const int tx = tid & 15, ty = tid >> 4;
    const int row0 = by * BM, col0 = bx * BN;

    unsigned long long acc[8][2];
#pragma unroll
    for (int i = 0; i < 8; i++) { acc[i][0] = 0ull; acc[i][1] = 0ull; }

    float4 va[2], vb;
    auto ldg = [&](int kt) {
#pragma unroll
        for (int i = 0; i < 2; i++) {
            int l = tid + i * 256;
            int ar = l >> 2, ac = (l & 3) * 4;
            va[i] = *(const float4*)&A[(size_t)(row0 + ar) * CC + kt + ac];
        }
        int br = tid >> 4, bc = (tid & 15) * 4;
        vb = *(const float4*)&B[(size_t)(kt + br) * CC + col0 + bc];
    };
    auto sts = [&](int s) {
#pragma unroll
        for (int i = 0; i < 2; i++) {
            int l = tid + i * 256;
            int ar = l >> 2, ac = (l & 3) * 4;
            As[s][ac + 0][ar] = va[i].x; As[s][ac + 1][ar] = va[i].y;
            As[s][ac + 2][ar] = va[i].z; As[s][ac + 3][ar] = va[i].w;
        }
        *(float4*)&Bs[s][tid >> 4][(tid & 15) * 4] = vb;
    };

    ldg(0);
    sts(0);
    __syncthreads();
    const int NT = 256 / BK;
    for (int c = 0; c < NT; c++) {
        const int s = c & 1;
        if (c + 1 < NT) ldg((c + 1) * BK);
#pragma unroll
        for (int k = 0; k < BK; k++) {
            float4 a0 = *(float4*)&As[s][k][ty * 8];
            float4 a1 = *(float4*)&As[s][k][ty * 8 + 4];
            unsigned long long b01 = *(unsigned long long*)&Bs[s][k][tx * 4];
            unsigned long long b23 = *(unsigned long long*)&Bs[s][k][tx * 4 + 2];
            float a[8] = {a0.x, a0.y, a0.z, a0.w, a1.x, a1.y, a1.z, a1.w};
#pragma unroll
            for (int i = 0; i < 8; i++) {
                unsigned long long ad = pk2(a[i], a[i]);
                ffma2(acc[i][0], ad, b01);
                ffma2(acc[i][1], ad, b23);
            }
        }
        if (c + 1 < NT) {
            sts(s ^ 1);
            __syncthreads();
        }
    }
#pragma unroll
    for (int i = 0; i < 8; i++) {
        int m = row0 + ty * 8 + i;
        int n = col0 + tx * 4;
        float v0, v1, v2, v3;
        upk2(acc[i][0], v0, v1);
        upk2(acc[i][1], v2, v3);
        float4 o = make_float4(v0 + bias[n], v1 + bias[n + 1],
                               v2 + bias[n + 2], v3 + bias[n + 3]);
        *(float4*)&g_xl[(size_t)m * CC + n] = o;
    }
}

// ---------------------------------------------------------------------------
// Double-buffered f32x2 SGEMM 2: out = [mean | x] @ [linl ; linr] + linl_b
__global__ __launch_bounds__(256) void sage_g2(
    const float* __restrict__ X, const float* __restrict__ Wl,
    const float* __restrict__ Wr, const float* __restrict__ bl,
    float* __restrict__ Cout) {
    __shared__ float As[2][BK][BM];
    __shared__ float Bs[2][BK][BN];
    const int bx = blockIdx.x, by = blockIdx.y;
    const int tid = threadIdx.x;
    const int tx = tid & 15, ty = tid >> 4;
    const int row0 = by * BM, col0 = bx * BN;

    unsigned long long acc[8][2];
#pragma unroll
    for (int i = 0; i < 8; i++) { acc[i][0] = 0ull; acc[i][1] = 0ull; }

    float4 va[2], vb;
    auto ldg = [&](int kt) {
        const bool first = (kt < 256);
#pragma unroll
        for (int i = 0; i < 2; i++) {
            int l = tid + i * 256;
            int ar = l >> 2, ac = (l & 3) * 4;
            int m = row0 + ar;
            va[i] = first
                ? *(const float4*)&g_sums[(size_t)m * CC + kt + ac]
                : *(const float4*)&X[(size_t)m * CC + (kt - 256) + ac];
        }
        int br = tid >> 4, bc = (tid & 15) * 4;
        const float* Bsrc = first ? Wl : Wr;
        int kk = first ? (kt + br) : (kt - 256 + br);
        vb = *(const float4*)&Bsrc[(size_t)kk * CC + col0 + bc];
    };
    auto sts = [&](int s) {
#pragma unroll
        for (int i = 0; i < 2; i++) {
            int l = tid + i * 256;
            int ar = l >> 2, ac = (l & 3) * 4;
            As[s][ac + 0][ar] = va[i].x; As[s][ac + 1][ar] = va[i].y;
            As[s][ac + 2][ar] = va[i].z; As[s][ac + 3][ar] = va[i].w;
        }
        *(float4*)&Bs[s][tid >> 4][(tid & 15) * 4] = vb;
    };

    ldg(0);
    sts(0);
    __syncthreads();
    const int NT = 512 / BK;
    for (int c = 0; c < NT; c++) {
        const int s = c & 1;
        if (c + 1 < NT) ldg((c + 1) * BK);
#pragma unroll
        for (int k = 0; k < BK; k++) {
            float4 a0 = *(float4*)&As[s][k][ty * 8];
            float4 a1 = *(float4*)&As[s][k][ty * 8 + 4];
            unsigned long long b01 = *(unsigned long long*)&Bs[s][k][tx * 4];
            unsigned long long b23 = *(unsigned long long*)&Bs[s][k][tx * 4 + 2];
            float a[8] = {a0.x, a0.y, a0.z, a0.w, a1.x, a1.y, a1.z, a1.w};
#pragma unroll
            for (int i = 0; i < 8; i++) {
                unsigned long long ad = pk2(a[i], a[i]);
                ffma2(acc[i][0], ad, b01);
                ffma2(acc[i][1], ad, b23);
            }
        }
        if (c + 1 < NT) {
            sts(s ^ 1);
            __syncthreads();
        }
    }
#pragma unroll
    for (int i = 0; i < 8; i++) {
        int m = row0 + ty * 8 + i;
        int n = col0 + tx * 4;
        float v0, v1, v2, v3;
        upk2(acc[i][0], v0, v1);
        upk2(acc[i][1], v2, v3);
        float4 o = make_float4(v0 + bl[n], v1 + bl[n + 1],
                               v2 + bl[n + 2], v3 + bl[n + 3]);
        *(float4*)&Cout[(size_t)m * CC + n] = o;
    }
}

// ---------------------------------------------------------------------------
// CSR aggregation v2: one WARP per dst node, 8 channels/thread (float4 x2).
// Uses precomputed g_emb. Writes per-node means (inv folded in).
__global__ __launch_bounds__(256) void sage_agg(
    const float* __restrict__ ew, const int* __restrict__ ei) {
    const int w = threadIdx.x >> 5, lane = threadIdx.x & 31;
    const int d = blockIdx.x * 8 + w;
    const int c0 = lane * 8;
    const int beg = g_off[d];
    const int end = (d == NN - 1) ? EE : g_off[d + 1];

    float acc[RC][8];
#pragma unroll
    for (int r = 0; r < RC; r++)
#pragma unroll
        for (int j = 0; j < 8; j++) acc[r][j] = 0.f;

    for (int p = beg; p < end; p++) {
        int e = g_eord[p];
        int s = ei[e];
        s = (s >= 0 && s < NN) ? s : 0;
        float4 em0 = *(const float4*)&g_emb[(size_t)e * CC + c0];
        float4 em1 = *(const float4*)&g_emb[(size_t)e * CC + c0 + 4];
        float wr[RC];
#pragma unroll
        for (int r = 0; r < RC; r++) wr[r] = ew[(size_t)r * EE + e];
#pragma unroll
        for (int r = 0; r < RC; r++) {
            const float* xr = &g_xl[((size_t)(r * NN + s)) * CC + c0];
            float4 x0 = *(const float4*)xr;
            float4 x1 = *(const float4*)(xr + 4);
            acc[r][0] += gelu(x0.x + em0.x) * wr[r];
            acc[r][1] += gelu(x0.y + em0.y) * wr[r];
            acc[r][2] += gelu(x0.z + em0.z) * wr[r];
            acc[r][3] += gelu(x0.w + em0.w) * wr[r];
            acc[r][4] += gelu(x1.x + em1.x) * wr[r];
            acc[r][5] += gelu(x1.y + em1.y) * wr[r];
            acc[r][6] += gelu(x1.z + em1.z) * wr[r];
            acc[r][7] += gelu(x1.w + em1.w) * wr[r];
        }
    }
    const float inv = g_inv[d];
#pragma unroll
    for (int r = 0; r < RC; r++) {
        float* dp = &g_sums[((size_t)(r * NN + d)) * CC + c0];
        *(float4*)dp = make_float4(acc[r][0] * inv, acc[r][1] * inv,
                                   acc[r][2] * inv, acc[r][3] * inv);
        *(float4*)(dp + 4) = make_float4(acc[r][4] * inv, acc[r][5] * inv,
                                         acc[r][6] * inv, acc[r][7] * inv);
    }
}

// ---------------------------------------------------------------------------
extern "C" void kernel_launch(void* const* d_in, const int* in_sizes, int n_in,
                              void* d_out, int out_size) {
    const float* x         = (const float*)d_in[0];
    const float* edge_attr = (const float*)d_in[1];
    const float* edge_w    = (const float*)d_in[2];
    const float* lin_W     = (const float*)d_in[3];
    const float* lin_b     = (const float*)d_in[4];
    const float* linl_W    = (const float*)d_in[5];
    const float* linl_b    = (const float*)d_in[6];
    const float* linr_W    = (const float*)d_in[7];
    const float* bond_W    = (const float*)d_in[8];
    const float* bond_b    = (const float*)d_in[9];
    const int*   eidx      = (const int*)d_in[10];
    float* out = (float*)d_out;

    // order chosen so sage_g1 is the 4th launch (the one ncu captures)
    sage_rst<<<(NN + 255) / 256, 256>>>();
    sage_cnt<<<(EE + 255) / 256, 256>>>(eidx);
    sage_scan<<<1, SCAN_T>>>();
    sage_g1<<<dim3(CC / BN, MROWS / BM), 256>>>(x, lin_W, lin_b);
    sage_place<<<(EE + 255) / 256, 256>>>(eidx);
    sage_emb<<<EE * 64 / 256, 256>>>(edge_attr, bond_W, bond_b);
    sage_agg<<<NN / 8, 256>>>(edge_w, eidx);
    sage_g2<<<dim3(CC / BN, MROWS / BM), 256>>>(x, linl_W, linr_W, linl_b, out);
}

// round 14
// speedup vs baseline: 1.0728x; 1.0642x over previous
#include <cuda_runtime.h>
#include <cstdint>

#define NN 20000
#define EE 100000
#define CC 256
#define ED_ 16
#define RC 4
#define MROWS 80000

// Scratch (device globals: no allocation allowed)
__device__ float g_xl[(size_t)MROWS * CC];
__device__ float g_sums[(size_t)MROWS * CC];   // per-node MEAN after sage_agg
__device__ float g_emb[(size_t)EE * CC];       // bond encoder output
__device__ float g_inv[NN];
__device__ int   g_cnt[NN];
__device__ int   g_cur[NN];
__device__ int   g_off[NN];
__device__ int   g_eord[EE];

// ---------------------------------------------------------------------------
// packed fp32x2 helpers (SASS FFMA2) — proven in R10
__device__ __forceinline__ unsigned long long pk2(float lo, float hi) {
    unsigned long long r;
    asm("mov.b64 %0, {%1, %2};" : "=l"(r) : "f"(lo), "f"(hi));
    return r;
}
__device__ __forceinline__ void upk2(unsigned long long v, float& lo, float& hi) {
    asm("mov.b64 {%0, %1}, %2;" : "=f"(lo), "=f"(hi) : "l"(v));
}
__device__ __forceinline__ void ffma2(unsigned long long& d, unsigned long long a,
                                      unsigned long long b) {
    asm("fma.rn.f32x2 %0, %1, %2, %0;" : "+l"(d) : "l"(a), "l"(b));
}

__device__ __forceinline__ float gelu(float t) {
    return 0.5f * t * (1.0f + erff(t * 0.70710678118654752f));
}

// ---------------------------------------------------------------------------
// CSR build: reset, count, scan(+inv), place  (proven in R12)
__global__ void sage_rst() {
    int n = blockIdx.x * blockDim.x + threadIdx.x;
    if (n < NN) { g_cnt[n] = 0; g_cur[n] = 0; }
}

__global__ void sage_cnt(const int* __restrict__ ei) {
    int e = blockIdx.x * blockDim.x + threadIdx.x;
    if (e < EE) {
        int d = ei[EE + e];
        d = (d >= 0 && d < NN) ? d : 0;
        atomicAdd(&g_cnt[d], 1);
    }
}

#define SCAN_T 1024
__global__ __launch_bounds__(SCAN_T) void sage_scan() {
    __shared__ int ps[SCAN_T];
    const int t = threadIdx.x;
    const int CHN = (NN + SCAN_T - 1) / SCAN_T;
    const int base = t * CHN;
    int sum = 0;
    for (int i = 0; i < CHN; i++) {
        int n = base + i;
        if (n < NN) sum += g_cnt[n];
    }
    ps[t] = sum;
    __syncthreads();
    for (int d = 1; d < SCAN_T; d <<= 1) {
        int v = (t >= d) ? ps[t - d] : 0;
        __syncthreads();
        ps[t] += v;
        __syncthreads();
    }
    int run = (t == 0) ? 0 : ps[t - 1];
    for (int i = 0; i < CHN; i++) {
        int n = base + i;
        if (n < NN) {
            int c = g_cnt[n];
            g_off[n] = run;
            run += c;
            g_inv[n] = 1.0f / fmaxf((float)c, 1.0f);
        }
    }
}

__global__ void sage_place(const int* __restrict__ ei) {
    int e = blockIdx.x * blockDim.x + threadIdx.x;
    if (e < EE) {
        int d = ei[EE + e];
        d = (d >= 0 && d < NN) ? d : 0;
        int p = g_off[d] + atomicAdd(&g_cur[d], 1);
        g_eord[p] = e;
    }
}

// ---------------------------------------------------------------------------
// Bond encoder precompute: g_emb[e][c] = bond_b[c] + sum_k ea[e][k]*bond_W[k][c]
__global__ __launch_bounds__(256) void sage_emb(
    const float* __restrict__ ea, const float* __restrict__ bw,
    const float* __restrict__ bb) {
    int idx = blockIdx.x * 256 + threadIdx.x;   // EE*64 total
    int e = idx >> 6, cq = (idx & 63) * 4;
    if (e < EE) {
        float4 acc = *(const float4*)&bb[cq];
#pragma unroll
        for (int k = 0; k < ED_; k++) {
            float a = ea[(size_t)e * ED_ + k];
            float4 w = *(const float4*)&bw[k * CC + cq];
            acc.x += a * w.x; acc.y += a * w.y;
            acc.z += a * w.z; acc.w += a * w.w;
        }
        *(float4*)&g_emb[(size_t)e * CC + cq] = acc;
    }
}

// ---------------------------------------------------------------------------
// Double-buffered f32x2 SGEMM 1: g_xl = x @ lin_W + lin_b (M=80000,N=256,K=256)
#define BM 128
#define BN 64
#define BK 16

__global__ __launch_bounds__(256) void sage_g1(
    const float* __restrict__ A, const float* __restrict__ B,
    const float* __restrict__ bias) {
    __shared__ float As[2][BK][BM];
    __shared__ float Bs[2][BK][BN];
    const int bx = blockIdx.x, by = blockIdx.y;
    const int tid = threadIdx.x;
    const int tx = tid & 15, ty = tid >> 4;
    const int row0 = by * BM, col0 = bx * BN;

    unsigned long long acc[8][2];
#pragma unroll
    for (int i = 0; i < 8; i++) { acc[i][0] = 0ull; acc[i][1] = 0ull; }

    float4 va[2], vb;
    auto ldg = [&](int kt) {
#pragma unroll
        for (int i = 0; i < 2; i++) {
            int l = tid + i * 256;
            int ar = l >> 2, ac = (l & 3) * 4;
            va[i] = *(const float4*)&A[(size_t)(row0 + ar) * CC + kt + ac];
        }
        int br = tid >> 4, bc = (tid & 15) * 4;
        vb = *(const float4*)&B[(size_t)(kt + br) * CC + col0 + bc];
    };
    auto sts = [&](int s) {
#pragma unroll
        for (int i = 0; i < 2; i++) {
            int l = tid + i * 256;
            int ar = l >> 2, ac = (l & 3) * 4;
            As[s][ac + 0][ar] = va[i].x; As[s][ac + 1][ar] = va[i].y;
            As[s][ac + 2][ar] = va[i].z; As[s][ac + 3][ar] = va[i].w;
        }
        *(float4*)&Bs[s][tid >> 4][(tid & 15) * 4] = vb;
    };

    ldg(0);
    sts(0);
    __syncthreads();
    const int NT = 256 / BK;
    for (int c = 0; c < NT; c++) {
        const int s = c & 1;
        if (c + 1 < NT) ldg((c + 1) * BK);
#pragma unroll
        for (int k = 0; k < BK; k++) {
            float4 a0 = *(float4*)&As[s][k][ty * 8];
            float4 a1 = *(float4*)&As[s][k][ty * 8 + 4];
            unsigned long long b01 = *(unsigned long long*)&Bs[s][k][tx * 4];
            unsigned long long b23 = *(unsigned long long*)&Bs[s][k][tx * 4 + 2];
            float a[8] = {a0.x, a0.y, a0.z, a0.w, a1.x, a1.y, a1.z, a1.w};
#pragma unroll
            for (int i = 0; i < 8; i++) {
                unsigned long long ad = pk2(a[i], a[i]);
                ffma2(acc[i][0], ad, b01);
                ffma2(acc[i][1], ad, b23);
            }
        }
        if (c + 1 < NT) {
            sts(s ^ 1);
            __syncthreads();
        }
    }
#pragma unroll
    for (int i = 0; i < 8; i++) {
        int m = row0 + ty * 8 + i;
        int n = col0 + tx * 4;
        float v0, v1, v2, v3;
        upk2(acc[i][0], v0, v1);
        upk2(acc[i][1], v2, v3);
        float4 o = make_float4(v0 + bias[n], v1 + bias[n + 1],
                               v2 + bias[n + 2], v3 + bias[n + 3]);
        *(float4*)&g_xl[(size_t)m * CC + n] = o;
    }
}

// ---------------------------------------------------------------------------
// Double-buffered f32x2 SGEMM 2: out = [mean | x] @ [linl ; linr] + linl_b
__global__ __launch_bounds__(256) void sage_g2(
    const float* __restrict__ X, const float* __restrict__ Wl,
    const float* __restrict__ Wr, const float* __restrict__ bl,
    float* __restrict__ Cout) {
    __shared__ float As[2][BK][BM];
    __shared__ float Bs[2][BK][BN];
    const int bx = blockIdx.x, by = blockIdx.y;
    const int tid = threadIdx.x;
    const int tx = tid & 15, ty = tid >> 4;
    const int row0 = by * BM, col0 = bx * BN;

    unsigned long long acc[8][2];
#pragma unroll
    for (int i = 0; i < 8; i++) { acc[i][0] = 0ull; acc[i][1] = 0ull; }

    float4 va[2], vb;
    auto ldg = [&](int kt) {
        const bool first = (kt < 256);
#pragma unroll
        for (int i = 0; i < 2; i++) {
            int l = tid + i * 256;
            int ar = l >> 2, ac = (l & 3) * 4;
            int m = row0 + ar;
            va[i] = first
                ? *(const float4*)&g_sums[(size_t)m * CC + kt + ac]
                : *(const float4*)&X[(size_t)m * CC + (kt - 256) + ac];
        }
        int br = tid >> 4, bc = (tid & 15) * 4;
        const float* Bsrc = first ? Wl : Wr;
        int kk = first ? (kt + br) : (kt - 256 + br);
        vb = *(const float4*)&Bsrc[(size_t)kk * CC + col0 + bc];
    };
    auto sts = [&](int s) {
#pragma unroll
        for (int i = 0; i < 2; i++) {
            int l = tid + i * 256;
            int ar = l >> 2, ac = (l & 3) * 4;
            As[s][ac + 0][ar] = va[i].x; As[s][ac + 1][ar] = va[i].y;
            As[s][ac + 2][ar] = va[i].z; As[s][ac + 3][ar] = va[i].w;
        }
        *(float4*)&Bs[s][tid >> 4][(tid & 15) * 4] = vb;
    };

    ldg(0);
    sts(0);
    __syncthreads();
    const int NT = 512 / BK;
    for (int c = 0; c < NT; c++) {
        const int s = c & 1;
        if (c + 1 < NT) ldg((c + 1) * BK);
#pragma unroll
        for (int k = 0; k < BK; k++) {
            float4 a0 = *(float4*)&As[s][k][ty * 8];
            float4 a1 = *(float4*)&As[s][k][ty * 8 + 4];
            unsigned long long b01 = *(unsigned long long*)&Bs[s][k][tx * 4];
            unsigned long long b23 = *(unsigned long long*)&Bs[s][k][tx * 4 + 2];
            float a[8] = {a0.x, a0.y, a0.z, a0.w, a1.x, a1.y, a1.z, a1.w};
#pragma unroll
            for (int i = 0; i < 8; i++) {
                unsigned long long ad = pk2(a[i], a[i]);
                ffma2(acc[i][0], ad, b01);
                ffma2(acc[i][1], ad, b23);
            }
        }
        if (c + 1 < NT) {
            sts(s ^ 1);
            __syncthreads();
        }
    }
#pragma unroll
    for (int i = 0; i < 8; i++) {
        int m = row0 + ty * 8 + i;
        int n = col0 + tx * 4;
        float v0, v1, v2, v3;
        upk2(acc[i][0], v0, v1);
        upk2(acc[i][1], v2, v3);
        float4 o = make_float4(v0 + bl[n], v1 + bl[n + 1],
                               v2 + bl[n + 2], v3 + bl[n + 3]);
        *(float4*)&Cout[(size_t)m * CC + n] = o;
    }
}

// ---------------------------------------------------------------------------
// CSR aggregation v3: one WARP per (node, replica); 80K warps; software-
// pipelined edge index chain; 8 channels/thread (2x float4).
__global__ __launch_bounds__(256) void sage_agg(
    const float* __restrict__ ew, const int* __restrict__ ei) {
    const int w = threadIdx.x >> 5, lane = threadIdx.x & 31;
    const int gw = blockIdx.x * 8 + w;       // 0..79999
    const int d = gw >> 2, r = gw & 3;       // adjacent warps share node d
    const int c0 = lane * 8;
    const int beg = g_off[d];
    const int end = (d == NN - 1) ? EE : g_off[d + 1];

    float acc[8];
#pragma unroll
    for (int j = 0; j < 8; j++) acc[j] = 0.f;

    // software pipeline the e/s index chain
    int e_nx = (beg < end) ? g_eord[beg] : 0;
    int s_nx = (beg < end) ? ei[e_nx] : 0;
    for (int p = beg; p < end; p++) {
        const int e = e_nx;
        int s = s_nx;
        if (p + 1 < end) {
            e_nx = g_eord[p + 1];
            s_nx = ei[e_nx];
        }
        s = (s >= 0 && s < NN) ? s : 0;
        const float wgt = ew[(size_t)r * EE + e];
        const float4 em0 = *(const float4*)&g_emb[(size_t)e * CC + c0];
        const float4 em1 = *(const float4*)&g_emb[(size_t)e * CC + c0 + 4];
        const float* xr = &g_xl[((size_t)(r * NN + s)) * CC + c0];
        const float4 x0 = *(const float4*)xr;
        const float4 x1 = *(const float4*)(xr + 4);
        acc[0] += gelu(x0.x + em0.x) * wgt;
        acc[1] += gelu(x0.y + em0.y) * wgt;
        acc[2] += gelu(x0.z + em0.z) * wgt;
        acc[3] += gelu(x0.w + em0.w) * wgt;
        acc[4] += gelu(x1.x + em1.x) * wgt;
        acc[5] += gelu(x1.y + em1.y) * wgt;
        acc[6] += gelu(x1.z + em1.z) * wgt;
        acc[7] += gelu(x1.w + em1.w) * wgt;
    }
    const float inv = g_inv[d];
    float* dp = &g_sums[((size_t)(r * NN + d)) * CC + c0];
    *(float4*)dp = make_float4(acc[0] * inv, acc[1] * inv,
                               acc[2] * inv, acc[3] * inv);
    *(float4*)(dp + 4) = make_float4(acc[4] * inv, acc[5] * inv,
                                     acc[6] * inv, acc[7] * inv);
}

// ---------------------------------------------------------------------------
extern "C" void kernel_launch(void* const* d_in, const int* in_sizes, int n_in,
                              void* d_out, int out_size) {
    const float* x         = (const float*)d_in[0];
    const float* edge_attr = (const float*)d_in[1];
    const float* edge_w    = (const float*)d_in[2];
    const float* lin_W     = (const float*)d_in[3];
    const float* lin_b     = (const float*)d_in[4];
    const float* linl_W    = (const float*)d_in[5];
    const float* linl_b    = (const float*)d_in[6];
    const float* linr_W    = (const float*)d_in[7];
    const float* bond_W    = (const float*)d_in[8];
    const float* bond_b    = (const float*)d_in[9];
    const int*   eidx      = (const int*)d_in[10];
    float* out = (float*)d_out;

    sage_rst<<<(NN + 255) / 256, 256>>>();
    sage_cnt<<<(EE + 255) / 256, 256>>>(eidx);
    sage_scan<<<1, SCAN_T>>>();
    sage_g1<<<dim3(CC / BN, MROWS / BM), 256>>>(x, lin_W, lin_b);
    sage_place<<<(EE + 255) / 256, 256>>>(eidx);
    sage_emb<<<EE * 64 / 256, 256>>>(edge_attr, bond_W, bond_b);
    sage_agg<<<NN * 4 / 8, 256>>>(edge_w, eidx);
    sage_g2<<<dim3(CC / BN, MROWS / BM), 256>>>(x, linl_W, linr_W, linl_b, out);
}

// round 15
// speedup vs baseline: 1.0775x; 1.0044x over previous
#include <cuda_runtime.h>
#include <cstdint>

#define NN 20000
#define EE 100000
#define CC 256
#define ED_ 16
#define RC 4
#define MROWS 80000

// Scratch (device globals: no allocation allowed)
__device__ float g_xl[(size_t)MROWS * CC];
__device__ float g_sums[(size_t)MROWS * CC];   // per-node MEAN after sage_agg
__device__ float g_emb[(size_t)EE * CC];       // bond encoder output
__device__ float g_inv[NN];
__device__ int   g_cnt[NN];
__device__ int   g_cur[NN];
__device__ int   g_off[NN];
__device__ int   g_eord[EE];

// ---------------------------------------------------------------------------
// packed fp32x2 helpers (SASS FFMA2) — proven in R10
__device__ __forceinline__ unsigned long long pk2(float lo, float hi) {
    unsigned long long r;
    asm("mov.b64 %0, {%1, %2};" : "=l"(r) : "f"(lo), "f"(hi));
    return r;
}
__device__ __forceinline__ void upk2(unsigned long long v, float& lo, float& hi) {
    asm("mov.b64 {%0, %1}, %2;" : "=f"(lo), "=f"(hi) : "l"(v));
}
__device__ __forceinline__ void ffma2(unsigned long long& d, unsigned long long a,
                                      unsigned long long b) {
    asm("fma.rn.f32x2 %0, %1, %2, %0;" : "+l"(d) : "l"(a), "l"(b));
}

__device__ __forceinline__ float gelu(float t) {
    return 0.5f * t * (1.0f + erff(t * 0.70710678118654752f));
}

// ---------------------------------------------------------------------------
// CSR build: reset, count, scan(+inv), place  (proven in R12)
__global__ void sage_rst() {
    int n = blockIdx.x * blockDim.x + threadIdx.x;
    if (n < NN) { g_cnt[n] = 0; g_cur[n] = 0; }
}

__global__ void sage_cnt(const int* __restrict__ ei) {
    int e = blockIdx.x * blockDim.x + threadIdx.x;
    if (e < EE) {
        int d = ei[EE + e];
        d = (d >= 0 && d < NN) ? d : 0;
        atomicAdd(&g_cnt[d], 1);
    }
}

#define SCAN_T 1024
__global__ __launch_bounds__(SCAN_T) void sage_scan() {
    __shared__ int ps[SCAN_T];
    const int t = threadIdx.x;
    const int CHN = (NN + SCAN_T - 1) / SCAN_T;
    const int base = t * CHN;
    int sum = 0;
    for (int i = 0; i < CHN; i++) {
        int n = base + i;
        if (n < NN) sum += g_cnt[n];
    }
    ps[t] = sum;
    __syncthreads();
    for (int d = 1; d < SCAN_T; d <<= 1) {
        int v = (t >= d) ? ps[t - d] : 0;
        __syncthreads();
        ps[t] += v;
        __syncthreads();
    }
    int run = (t == 0) ? 0 : ps[t - 1];
    for (int i = 0; i < CHN; i++) {
        int n = base + i;
        if (n < NN) {
            int c = g_cnt[n];
            g_off[n] = run;
            run += c;
            g_inv[n] = 1.0f / fmaxf((float)c, 1.0f);
        }
    }
}

__global__ void sage_place(const int* __restrict__ ei) {
    int e = blockIdx.x * blockDim.x + threadIdx.x;
    if (e < EE) {
        int d = ei[EE + e];
        d = (d >= 0 && d < NN) ? d : 0;
        int p = g_off[d] + atomicAdd(&g_cur[d], 1);
        g_eord[p] = e;
    }
}

// ---------------------------------------------------------------------------
// Bond encoder precompute: g_emb[e][c] = bond_b[c] + sum_k ea[e][k]*bond_W[k][c]
__global__ __launch_bounds__(256) void sage_emb(
    const float* __restrict__ ea, const float* __restrict__ bw,
    const float* __restrict__ bb) {
    int idx = blockIdx.x * 256 + threadIdx.x;   // EE*64 total
    int e = idx >> 6, cq = (idx & 63) * 4;
    if (e < EE) {
        float4 acc = *(const float4*)&bb[cq];
#pragma unroll
        for (int k = 0; k < ED_; k++) {
            float a = ea[(size_t)e * ED_ + k];
            float4 w = *(const float4*)&bw[k * CC + cq];
            acc.x += a * w.x; acc.y += a * w.y;
            acc.z += a * w.z; acc.w += a * w.w;
        }
        *(float4*)&g_emb[(size_t)e * CC + cq] = acc;
    }
}

// ---------------------------------------------------------------------------
// Double-buffered f32x2 SGEMM 1: g_xl = x @ lin_W + lin_b (M=80000,N=256,K=256)
#define BM 128
#define BN 64
#define BK 16

__global__ __launch_bounds__(256) void sage_g1(
    const float* __restrict__ A, const float* __restrict__ B,
    const float* __restrict__ bias) {
    __shared__ float As[2][BK][BM];
    __shared__ float Bs[2][BK][BN];
    const int bx = blockIdx.x, by = blockIdx.y;
    const int tid = threadIdx.x;
    const int tx = tid & 15, ty = tid >> 4;
    const int row0 = by * BM, col0 = bx * BN;

    unsigned long long acc[8][2];
#pragma unroll
    for (int i = 0; i < 8; i++) { acc[i][0] = 0ull; acc[i][1] = 0ull; }

    float4 va[2], vb;
    auto ldg = [&](int kt) {
#pragma unroll
        for (int i = 0; i < 2; i++) {
            int l = tid + i * 256;
            int ar = l >> 2, ac = (l & 3) * 4;
            va[i] = *(const float4*)&A[(size_t)(row0 + ar) * CC + kt + ac];
        }
        int br = tid >> 4, bc = (tid & 15) * 4;
        vb = *(const float4*)&B[(size_t)(kt + br) * CC + col0 + bc];
    };
    auto sts = [&](int s) {
#pragma unroll
        for (int i = 0; i < 2; i++) {
            int l = tid + i * 256;
            int ar = l >> 2, ac = (l & 3) * 4;
            As[s][ac + 0][ar] = va[i].x; As[s][ac + 1][ar] = va[i].y;
            As[s][ac + 2][ar] = va[i].z; As[s][ac + 3][ar] = va[i].w;
        }
        *(float4*)&Bs[s][tid >> 4][(tid & 15) * 4] = vb;
    };

    ldg(0);
    sts(0);
    __syncthreads();
    const int NT = 256 / BK;
    for (int c = 0; c < NT; c++) {
        const int s = c & 1;
        if (c + 1 < NT) ldg((c + 1) * BK);
#pragma unroll
        for (int k = 0; k < BK; k++) {
            float4 a0 = *(float4*)&As[s][k][ty * 8];
            float4 a1 = *(float4*)&As[s][k][ty * 8 + 4];
            unsigned long long b01 = *(unsigned long long*)&Bs[s][k][tx * 4];
            unsigned long long b23 = *(unsigned long long*)&Bs[s][k][tx * 4 + 2];
            float a[8] = {a0.x, a0.y, a0.z, a0.w, a1.x, a1.y, a1.z, a1.w};
#pragma unroll
            for (int i = 0; i < 8; i++) {
                unsigned long long ad = pk2(a[i], a[i]);
                ffma2(acc[i][0], ad, b01);
                ffma2(acc[i][1], ad, b23);
            }
        }
        if (c + 1 < NT) {
            sts(s ^ 1);
            __syncthreads();
        }
    }
#pragma unroll
    for (int i = 0; i < 8; i++) {
        int m = row0 + ty * 8 + i;
        int n = col0 + tx * 4;
        float v0, v1, v2, v3;
        upk2(acc[i][0], v0, v1);
        upk2(acc[i][1], v2, v3);
        float4 o = make_float4(v0 + bias[n], v1 + bias[n + 1],
                               v2 + bias[n + 2], v3 + bias[n + 3]);
        *(float4*)&g_xl[(size_t)m * CC + n] = o;
    }
}

// ---------------------------------------------------------------------------
// Double-buffered f32x2 SGEMM 2: out = [mean | x] @ [linl ; linr] + linl_b
__global__ __launch_bounds__(256) void sage_g2(
    const float* __restrict__ X, const float* __restrict__ Wl,
    const float* __restrict__ Wr, const float* __restrict__ bl,
    float* __restrict__ Cout) {
    __shared__ float As[2][BK][BM];
    __shared__ float Bs[2][BK][BN];
    const int bx = blockIdx.x, by = blockIdx.y;
    const int tid = threadIdx.x;
    const int tx = tid & 15, ty = tid >> 4;
    const int row0 = by * BM, col0 = bx * BN;

    unsigned long long acc[8][2];
#pragma unroll
    for (int i = 0; i < 8; i++) { acc[i][0] = 0ull; acc[i][1] = 0ull; }

    float4 va[2], vb;
    auto ldg = [&](int kt) {
        const bool first = (kt < 256);
#pragma unroll
        for (int i = 0; i < 2; i++) {
            int l = tid + i * 256;
            int ar = l >> 2, ac = (l & 3) * 4;
            int m = row0 + ar;
            va[i] = first
                ? *(const float4*)&g_sums[(size_t)m * CC + kt + ac]
                : *(const float4*)&X[(size_t)m * CC + (kt - 256) + ac];
        }
        int br = tid >> 4, bc = (tid & 15) * 4;
        const float* Bsrc = first ? Wl : Wr;
        int kk = first ? (kt + br) : (kt - 256 + br);
        vb = *(const float4*)&Bsrc[(size_t)kk * CC + col0 + bc];
    };
    auto sts = [&](int s) {
#pragma unroll
        for (int i = 0; i < 2; i++) {
            int l = tid + i * 256;
            int ar = l >> 2, ac = (l & 3) * 4;
            As[s][ac + 0][ar] = va[i].x; As[s][ac + 1][ar] = va[i].y;
            As[s][ac + 2][ar] = va[i].z; As[s][ac + 3][ar] = va[i].w;
        }
        *(float4*)&Bs[s][tid >> 4][(tid & 15) * 4] = vb;
    };

    ldg(0);
    sts(0);
    __syncthreads();
    const int NT = 512 / BK;
    for (int c = 0; c < NT; c++) {
        const int s = c & 1;
        if (c + 1 < NT) ldg((c + 1) * BK);
#pragma unroll
        for (int k = 0; k < BK; k++) {
            float4 a0 = *(float4*)&As[s][k][ty * 8];
            float4 a1 = *(float4*)&As[s][k][ty * 8 + 4];
            unsigned long long b01 = *(unsigned long long*)&Bs[s][k][tx * 4];
            unsigned long long b23 = *(unsigned long long*)&Bs[s][k][tx * 4 + 2];
            float a[8] = {a0.x, a0.y, a0.z, a0.w, a1.x, a1.y, a1.z, a1.w};
#pragma unroll
            for (int i = 0; i < 8; i++) {
                unsigned long long ad = pk2(a[i], a[i]);
                ffma2(acc[i][0], ad, b01);
                ffma2(acc[i][1], ad, b23);
            }
        }
        if (c + 1 < NT) {
            sts(s ^ 1);
            __syncthreads();
        }
    }
#pragma unroll
    for (int i = 0; i < 8; i++) {
        int m = row0 + ty * 8 + i;
        int n = col0 + tx * 4;
        float v0, v1, v2, v3;
        upk2(acc[i][0], v0, v1);
        upk2(acc[i][1], v2, v3);
        float4 o = make_float4(v0 + bl[n], v1 + bl[n + 1],
                               v2 + bl[n + 2], v3 + bl[n + 3]);
        *(float4*)&Cout[(size_t)m * CC + n] = o;
    }
}

// ---------------------------------------------------------------------------
// CSR aggregation v3: one WARP per (node, replica); 80K warps; software-
// pipelined edge index chain; 8 channels/thread (2x float4).
__global__ __launch_bounds__(256) void sage_agg(
    const float* __restrict__ ew, const int* __restrict__ ei) {
    const int w = threadIdx.x >> 5, lane = threadIdx.x & 31;
    const int gw = blockIdx.x * 8 + w;       // 0..79999
    const int d = gw >> 2, r = gw & 3;       // adjacent warps share node d
    const int c0 = lane * 8;
    const int beg = g_off[d];
    const int end = (d == NN - 1) ? EE : g_off[d + 1];

    float acc[8];
#pragma unroll
    for (int j = 0; j < 8; j++) acc[j] = 0.f;

    // software pipeline the e/s index chain
    int e_nx = (beg < end) ? g_eord[beg] : 0;
    int s_nx = (beg < end) ? ei[e_nx] : 0;
    for (int p = beg; p < end; p++) {
        const int e = e_nx;
        int s = s_nx;
        if (p + 1 < end) {
            e_nx = g_eord[p + 1];
            s_nx = ei[e_nx];
        }
        s = (s >= 0 && s < NN) ? s : 0;
        const float wgt = ew[(size_t)r * EE + e];
        const float4 em0 = *(const float4*)&g_emb[(size_t)e * CC + c0];
        const float4 em1 = *(const float4*)&g_emb[(size_t)e * CC + c0 + 4];
        const float* xr = &g_xl[((size_t)(r * NN + s)) * CC + c0];
        const float4 x0 = *(const float4*)xr;
        const float4 x1 = *(const float4*)(xr + 4);
        acc[0] += gelu(x0.x + em0.x) * wgt;
        acc[1] += gelu(x0.y + em0.y) * wgt;
        acc[2] += gelu(x0.z + em0.z) * wgt;
        acc[3] += gelu(x0.w + em0.w) * wgt;
        acc[4] += gelu(x1.x + em1.x) * wgt;
        acc[5] += gelu(x1.y + em1.y) * wgt;
        acc[6] += gelu(x1.z + em1.z) * wgt;
        acc[7] += gelu(x1.w + em1.w) * wgt;
    }
    const float inv = g_inv[d];
    float* dp = &g_sums[((size_t)(r * NN + d)) * CC + c0];
    *(float4*)dp = make_float4(acc[0] * inv, acc[1] * inv,
                               acc[2] * inv, acc[3] * inv);
    *(float4*)(dp + 4) = make_float4(acc[4] * inv, acc[5] * inv,
                                     acc[6] * inv, acc[7] * inv);
}

// ---------------------------------------------------------------------------
extern "C" void kernel_launch(void* const* d_in, const int* in_sizes, int n_in,
                              void* d_out, int out_size) {
    const float* x         = (const float*)d_in[0];
    const float* edge_attr = (const float*)d_in[1];
    const float* edge_w    = (const float*)d_in[2];
    const float* lin_W     = (const float*)d_in[3];
    const float* lin_b     = (const float*)d_in[4];
    const float* linl_W    = (const float*)d_in[5];
    const float* linl_b    = (const float*)d_in[6];
    const float* linr_W    = (const float*)d_in[7];
    const float* bond_W    = (const float*)d_in[8];
    const float* bond_b    = (const float*)d_in[9];
    const int*   eidx      = (const int*)d_in[10];
    float* out = (float*)d_out;

    sage_rst<<<(NN + 255) / 256, 256>>>();
    sage_cnt<<<(EE + 255) / 256, 256>>>(eidx);
    sage_scan<<<1, SCAN_T>>>();
    sage_g1<<<dim3(CC / BN, MROWS / BM), 256>>>(x, lin_W, lin_b);
    sage_place<<<(EE + 255) / 256, 256>>>(eidx);
    sage_emb<<<EE * 64 / 256, 256>>>(edge_attr, bond_W, bond_b);
    sage_agg<<<NN * 4 / 8, 256>>>(edge_w, eidx);
    sage_g2<<<dim3(CC / BN, MROWS / BM), 256>>>(x, linl_W, linr_W, linl_b, out);
}